// round 7
// baseline (speedup 1.0000x reference)
#include <cuda_runtime.h>

#define B 384
#define DIM 1024
#define MARGIN 1.0f

// Scratch (no allocations allowed in kernel_launch)
__device__ float g_sq[B];
__device__ int   g_lab[B];
__device__ float g_D[B * B];
__device__ double g_total;
__device__ unsigned long long g_count;

// Kernel 1: per-row squared norms + label decode + zero accumulators.
// 384 blocks x 256 threads; block b reduces row b of embeddings.
// Block 0 additionally decodes labels (int32 vs int64 sniff) into g_lab.
__global__ void prep_kernel(const float* __restrict__ emb,
                            const int* __restrict__ lab_raw) {
    int row = blockIdx.x;
    const float4* e = (const float4*)(emb + (size_t)row * DIM);
    float s = 0.f;
    for (int i = threadIdx.x; i < DIM / 4; i += blockDim.x) {
        float4 v = e[i];
        s += v.x * v.x + v.y * v.y + v.z * v.z + v.w * v.w;
    }
    #pragma unroll
    for (int o = 16; o; o >>= 1) s += __shfl_down_sync(0xffffffffu, s, o);
    __shared__ float wsum[8];
    if ((threadIdx.x & 31) == 0) wsum[threadIdx.x >> 5] = s;
    __syncthreads();
    if (threadIdx.x == 0) {
        float t = 0.f;
        #pragma unroll
        for (int w = 0; w < 8; w++) t += wsum[w];
        g_sq[row] = t;
        if (row == 0) { g_total = 0.0; g_count = 0ull; }
    }

    if (blockIdx.x == 0) {
        // Dtype sniff: labels are values in [0,16). If the buffer is int64,
        // every odd 32-bit word among the first 384 words is a (zero) high
        // word. If int32, those words are random labels — all-zero has
        // probability 16^-192. Both probes stay within the int32 buffer size.
        __shared__ int not64;
        if (threadIdx.x == 0) not64 = 0;
        __syncthreads();
        for (int i = threadIdx.x; i < B / 2; i += blockDim.x)
            if (lab_raw[2 * i + 1] != 0) atomicOr(&not64, 1);
        __syncthreads();
        bool is64 = (not64 == 0);
        for (int i = threadIdx.x; i < B; i += blockDim.x)
            g_lab[i] = is64 ? lab_raw[2 * i] : lab_raw[i];
    }
}

// Kernel 2: D[a,n] = sq[a] + sq[n] - 2 * <e_a, e_n>, tiled 32x32, K-tiles of 32.
__global__ void dist_kernel(const float* __restrict__ emb) {
    __shared__ float As[32][33];
    __shared__ float Bs[32][33];
    int tx = threadIdx.x, ty = threadIdx.y;
    int rowA = blockIdx.y * 32 + ty;   // anchor index for loading
    int rowB = blockIdx.x * 32 + ty;   // column index for loading
    float acc = 0.f;
    for (int k0 = 0; k0 < DIM; k0 += 32) {
        As[ty][tx] = emb[(size_t)rowA * DIM + k0 + tx];
        Bs[ty][tx] = emb[(size_t)rowB * DIM + k0 + tx];
        __syncthreads();
        #pragma unroll
        for (int k = 0; k < 32; k++) acc += As[ty][k] * Bs[tx][k];
        __syncthreads();
    }
    int a = blockIdx.y * 32 + ty;
    int n = blockIdx.x * 32 + tx;
    g_D[a * B + n] = g_sq[a] + g_sq[n] - 2.f * acc;
}

// Kernel 3: per-anchor triplet reduction. One block per anchor a.
// sum over p>a (same label), n (diff label) of relu(D[a,p] - D[a,n] + margin).
__global__ void triplet_kernel() {
    __shared__ float Drow[B];
    __shared__ int lab[B];
    __shared__ double red[8];
    int a = blockIdx.x;
    for (int i = threadIdx.x; i < B; i += blockDim.x) {
        Drow[i] = g_D[a * B + i];
        lab[i] = g_lab[i];
    }
    __syncthreads();
    int la = lab[a];
    double acc = 0.0;
    for (int p = a + 1; p < B; p++) {
        if (lab[p] != la) continue;
        float x = Drow[p] + MARGIN;
        for (int n = threadIdx.x; n < B; n += blockDim.x) {
            if (lab[n] != la) {
                float t = x - Drow[n];
                if (t > 0.f) acc += (double)t;
            }
        }
    }
    #pragma unroll
    for (int o = 16; o; o >>= 1) acc += __shfl_down_sync(0xffffffffu, acc, o);
    if ((threadIdx.x & 31) == 0) red[threadIdx.x >> 5] = acc;
    __syncthreads();
    if (threadIdx.x == 0) {
        double s = 0.0;
        int nw = blockDim.x >> 5;
        for (int w = 0; w < nw; w++) s += red[w];
        int pc = 0, nc = 0;
        for (int i = 0; i < B; i++) {
            if (lab[i] != la) nc++;
            else if (i > a) pc++;
        }
        atomicAdd(&g_total, s);
        atomicAdd(&g_count, (unsigned long long)pc * (unsigned long long)nc);
    }
}

// Kernel 4: finalize — write mean (and count if the output has room).
__global__ void final_kernel(float* __restrict__ out, int out_size) {
    double mean = (g_count > 0ull) ? (g_total / (double)g_count) : 0.0;
    out[0] = (float)mean;
    if (out_size > 1) out[1] = (float)g_count;
}

extern "C" void kernel_launch(void* const* d_in, const int* in_sizes, int n_in,
                              void* d_out, int out_size) {
    const float* emb = (const float*)d_in[0];
    const int* lab_raw = (const int*)d_in[1];
    float* out = (float*)d_out;

    prep_kernel<<<B, 256>>>(emb, lab_raw);
    dim3 dgrid(B / 32, B / 32);
    dim3 dblk(32, 32);
    dist_kernel<<<dgrid, dblk>>>(emb);
    triplet_kernel<<<B, 256>>>();
    final_kernel<<<1, 1>>>(out, out_size);
}

// round 8
// speedup vs baseline: 1.8805x; 1.8805x over previous
#include <cuda_runtime.h>

#define Bn 384
#define DIM 1024
#define MARGIN 1.0f
#define TS 64      // output tile (TS x TS)
#define NT 6       // tiles per dimension (384/64)
#define KSPLIT 4   // k-split factor
#define KSL 256    // k per split (1024/4)
#define KT 32      // k-tile staged in smem

// Scratch (__device__ globals; no allocation in kernel_launch)
__device__ float g_sq[Bn];
__device__ int   g_lab[Bn];
__device__ float g_part[KSPLIT][Bn * Bn];   // -2 * partial Gram
__device__ double g_total;
__device__ unsigned long long g_count;
__device__ unsigned int g_done;             // zero-init; reset by finalizer

// ───────────────────────────────────────────────────────────────────────
// Kernel A (150 blocks x 256 thr):
//   blocks 0..143 : split-K GEMM, 64x64 tile, 4x4 register blocking,
//                   stores -2 * (partial dot) into its own slab.
//   blocks 144..149: row norms (64 rows each, 4 threads/row);
//                   block 144 also zeroes accumulators + decodes labels.
// ───────────────────────────────────────────────────────────────────────
__global__ void __launch_bounds__(256) fused_a(const float* __restrict__ emb,
                                               const int* __restrict__ lab_raw) {
    int bid = blockIdx.x;
    int tid = threadIdx.x;

    if (bid < 144) {
        // k-major transposed smem, pad 68 (272B rows -> 16B aligned)
        __shared__ float As[KT][68];
        __shared__ float Bs[KT][68];
        int ks   = bid & 3;
        int tile = bid >> 2;
        int a0 = (tile / NT) * TS;
        int n0 = (tile % NT) * TS;
        int k0 = ks * KSL;
        int tx = tid & 15, ty = tid >> 4;

        float acc[4][4] = {};
        for (int kt = 0; kt < KSL; kt += KT) {
            // stage 64 rows x 32 k of each operand (coalesced gmem reads)
            for (int i = tid; i < TS * KT; i += 256) {
                int m = i >> 5, kk = i & 31;
                As[kk][m] = emb[(size_t)(a0 + m) * DIM + k0 + kt + kk];
                Bs[kk][m] = emb[(size_t)(n0 + m) * DIM + k0 + kt + kk];
            }
            __syncthreads();
            #pragma unroll
            for (int kk = 0; kk < KT; kk++) {
                float4 a4 = *(const float4*)&As[kk][ty * 4];
                float4 b4 = *(const float4*)&Bs[kk][tx * 4];
                float av[4] = {a4.x, a4.y, a4.z, a4.w};
                float bv[4] = {b4.x, b4.y, b4.z, b4.w};
                #pragma unroll
                for (int i = 0; i < 4; i++)
                    #pragma unroll
                    for (int j = 0; j < 4; j++)
                        acc[i][j] += av[i] * bv[j];
            }
            __syncthreads();
        }
        // store -2 * partial (vectorized, coalesced)
        #pragma unroll
        for (int i = 0; i < 4; i++) {
            float4 v = make_float4(-2.f * acc[i][0], -2.f * acc[i][1],
                                   -2.f * acc[i][2], -2.f * acc[i][3]);
            *(float4*)&g_part[ks][(size_t)(a0 + ty * 4 + i) * Bn + n0 + tx * 4] = v;
        }
    } else {
        // norm blocks: 64 rows, 4 threads per row
        int nb  = bid - 144;
        int row = nb * 64 + (tid >> 2);
        int part = tid & 3;
        const float4* e = (const float4*)(emb + (size_t)row * DIM);
        float s = 0.f;
        #pragma unroll 8
        for (int j = 0; j < 64; j++) {
            float4 v = e[part * 64 + j];
            s += v.x * v.x + v.y * v.y + v.z * v.z + v.w * v.w;
        }
        s += __shfl_xor_sync(0xffffffffu, s, 1);
        s += __shfl_xor_sync(0xffffffffu, s, 2);
        if (part == 0) g_sq[row] = s;

        if (nb == 0) {
            if (tid == 0) { g_total = 0.0; g_count = 0ull; }
            // int64-vs-int32 label sniff (labels in [0,16): int64 high words
            // are all zero; for int32, P(all 192 odd words zero) = 16^-192).
            __shared__ int not64;
            if (tid == 0) not64 = 0;
            __syncthreads();
            for (int i = tid; i < Bn / 2; i += 256)
                if (lab_raw[2 * i + 1] != 0) atomicOr(&not64, 1);
            __syncthreads();
            bool is64 = (not64 == 0);
            for (int i = tid; i < Bn; i += 256)
                g_lab[i] = is64 ? lab_raw[2 * i] : lab_raw[i];
        }
    }
}

// ───────────────────────────────────────────────────────────────────────
// Kernel B (384 blocks x 384 thr): per-anchor triplet reduction + finalize.
// Thread tid owns negative candidate n = tid. F[a,n] = sq_n - 2*G[a,n]
// (anchor's own norm cancels in the difference).
// ───────────────────────────────────────────────────────────────────────
__global__ void __launch_bounds__(384) fused_b(float* __restrict__ out, int out_size) {
    __shared__ float Drow[Bn];
    __shared__ int lab[Bn];
    __shared__ double red[12];
    int a = blockIdx.x;
    int tid = threadIdx.x;

    {
        size_t off = (size_t)a * Bn + tid;
        Drow[tid] = g_part[0][off] + g_part[1][off] + g_part[2][off] +
                    g_part[3][off] + g_sq[tid];
        lab[tid] = g_lab[tid];
    }
    __syncthreads();

    int la = lab[a];
    float myD = Drow[tid];
    bool neg = (lab[tid] != la);
    double acc = 0.0;
    for (int p = a + 1; p < Bn; p++) {     // uniform branch across the block
        if (lab[p] != la) continue;
        float x = Drow[p] + MARGIN;
        if (neg) {
            float t = x - myD;
            if (t > 0.f) acc += (double)t;
        }
    }

    #pragma unroll
    for (int o = 16; o; o >>= 1) acc += __shfl_down_sync(0xffffffffu, acc, o);
    if ((tid & 31) == 0) red[tid >> 5] = acc;
    __syncthreads();

    if (tid == 0) {
        double s = 0.0;
        #pragma unroll
        for (int w = 0; w < 12; w++) s += red[w];
        int pc = 0, nc = 0;
        for (int i = 0; i < Bn; i++) {
            if (lab[i] != la) nc++;
            else if (i > a) pc++;
        }
        atomicAdd(&g_total, s);
        atomicAdd(&g_count, (unsigned long long)pc * (unsigned long long)nc);
        __threadfence();
        unsigned t = atomicAdd(&g_done, 1u);
        if (t == gridDim.x - 1) {          // last block finalizes
            double tot = atomicAdd(&g_total, 0.0);
            unsigned long long c = atomicAdd(&g_count, 0ull);
            double mean = (c > 0ull) ? tot / (double)c : 0.0;
            out[0] = (float)mean;
            if (out_size > 1) out[1] = (float)c;
            g_done = 0;                    // reset for next graph replay
        }
    }
}

extern "C" void kernel_launch(void* const* d_in, const int* in_sizes, int n_in,
                              void* d_out, int out_size) {
    const float* emb = (const float*)d_in[0];
    const int* lab_raw = (const int*)d_in[1];
    float* out = (float*)d_out;

    fused_a<<<150, 256>>>(emb, lab_raw);
    fused_b<<<Bn, Bn>>>(out, out_size);
}